// round 10
// baseline (speedup 1.0000x reference)
#include <cuda_runtime.h>
#include <cuda_bf16.h>
#include <math.h>

#define NSEQ 1024
#define CS   384
#define CZ   128
#define NH   16
#define DH   24
#define HC   384
#define NN   (NSEQ*NSEQ)
#define RSQRT_D 0.2041241452319315f

typedef unsigned long long u64;
typedef unsigned int u32;

__device__ __forceinline__ u64 pk2(float a, float b) {
    u64 r; asm("mov.b64 %0,{%1,%2};" : "=l"(r) : "f"(a), "f"(b)); return r;
}
__device__ __forceinline__ void upk2(u64 v, float& a, float& b) {
    asm("mov.b64 {%0,%1},%2;" : "=f"(a), "=f"(b) : "l"(v));
}
__device__ __forceinline__ u64 ffma2(u64 a, u64 b, u64 c) {
    u64 d; asm("fma.rn.f32x2 %0,%1,%2,%3;" : "=l"(d) : "l"(a), "l"(b), "l"(c)); return d;
}
__device__ __forceinline__ float sigm(float x) { return 1.0f / (1.0f + __expf(-x)); }
__device__ __forceinline__ u32 cvt_tf32(float x) {
    u32 r; asm("cvt.rna.tf32.f32 %0, %1;" : "=r"(r) : "f"(x)); return r;
}
__device__ __forceinline__ void mma_tf32(float* c, u32 a0, u32 a1, u32 a2, u32 a3,
                                         u32 b0, u32 b1) {
    asm("mma.sync.aligned.m16n8k8.row.col.f32.tf32.tf32.f32 "
        "{%0,%1,%2,%3},{%4,%5,%6,%7},{%8,%9},{%0,%1,%2,%3};"
        : "+f"(c[0]), "+f"(c[1]), "+f"(c[2]), "+f"(c[3])
        : "r"(a0), "r"(a1), "r"(a2), "r"(a3), "r"(b0), "r"(b1));
}

// ------------- scratch (static device globals) -------------
__device__ float g_aln[NSEQ * CS];
__device__ float g_sln[NSEQ * CS];
__device__ float g_a  [NSEQ * CS];
__device__ float g_q  [NH * NSEQ * DH];
__device__ float g_k  [NH * NSEQ * DH];
__device__ float g_v  [NH * NSEQ * DH];
__device__ float g_g  [NH * NSEQ * DH];
__device__ float g_bias[(size_t)NH * NN];   // [h][i][j], 64 MB
__device__ float g_o  [NSEQ * HC];
__device__ float g_gate[NSEQ * CS];
__device__ float g_wt[CZ * 24];             // tf32(lnw*wb), row stride 24
__device__ float g_WH[NH];
__device__ float g_CH[NH];

// =====================================================================
// Kernel P: prep pair-bias weights (tf32-converted, stride-24 layout).
// =====================================================================
__global__ void __launch_bounds__(128) k_prep(const float* __restrict__ lnw,
                                              const float* __restrict__ lnb,
                                              const float* __restrict__ wb) {
    int t = threadIdx.x;
    for (int idx = t; idx < CZ * 24; idx += 128) {
        int c = idx / 24, h = idx % 24;
        float v = (h < NH) ? lnw[c] * wb[c * NH + h] : 0.0f;
        g_wt[idx] = __uint_as_float(cvt_tf32(v));
    }
    if (t < NH) {
        float W = 0, C = 0;
        #pragma unroll 4
        for (int cc = 0; cc < CZ; cc++) {
            float wv = wb[cc * NH + t];
            W += lnw[cc] * wv; C += lnb[cc] * wv;
        }
        g_WH[t] = W; g_CH[t] = C;
    }
}

// =====================================================================
// Kernel 0: row layer norms of a_i and s_i.  grid 1024, block 384.
// =====================================================================
__global__ void __launch_bounds__(384) k_ln(const float* __restrict__ a_i,
                                            const float* __restrict__ s_i,
                                            const float* __restrict__ lnw) {
    __shared__ float red[12][4];
    __shared__ float bcv[4];
    int i = blockIdx.x, t = threadIdx.x;
    float av = a_i[i * CS + t];
    float sv = s_i[i * CS + t];
    float r0 = av, r1 = av * av, r2 = sv, r3 = sv * sv;
    #pragma unroll
    for (int o = 16; o > 0; o >>= 1) {
        r0 += __shfl_down_sync(0xffffffffu, r0, o);
        r1 += __shfl_down_sync(0xffffffffu, r1, o);
        r2 += __shfl_down_sync(0xffffffffu, r2, o);
        r3 += __shfl_down_sync(0xffffffffu, r3, o);
    }
    if ((t & 31) == 0) { int w = t >> 5; red[w][0]=r0; red[w][1]=r1; red[w][2]=r2; red[w][3]=r3; }
    __syncthreads();
    if (t == 0) {
        float s0=0, s1=0, s2=0, s3=0;
        #pragma unroll
        for (int w = 0; w < 12; w++) { s0+=red[w][0]; s1+=red[w][1]; s2+=red[w][2]; s3+=red[w][3]; }
        float ma = s0 * (1.0f/CS), ms = s2 * (1.0f/CS);
        float va = s1 * (1.0f/CS) - ma*ma;
        float vs = s3 * (1.0f/CS) - ms*ms;
        bcv[0]=ma; bcv[1]=rsqrtf(va + 1e-5f);
        bcv[2]=ms; bcv[3]=rsqrtf(vs + 1e-5f);
    }
    __syncthreads();
    g_aln[i*CS + t] = (av - bcv[0]) * bcv[1];
    g_sln[i*CS + t] = (sv - bcv[2]) * bcv[3] * lnw[t];
}

// =====================================================================
// Kernel 1: AdaLN. 16-row x 128-col tiles, block 256 (R8 shape).
// =====================================================================
#define ST20 20
#define ADA_SMEM ((CS*ST20 + 2*2*16*128) * 4)
__global__ void __launch_bounds__(256) k_adaln(const float* __restrict__ ws,
                                               const float* __restrict__ bs,
                                               const float* __restrict__ wns) {
    extern __shared__ float dsm[];
    float* st  = dsm;
    float* wbf = dsm + CS * ST20;
    int t  = threadIdx.x;
    int tx = t & 127, ty = t >> 7;
    int i0 = blockIdx.y * 16;
    int c0 = blockIdx.x * 128;
    int c  = c0 + tx;

    for (int r = 0; r < 16; r++)
        for (int kk = t; kk < CS; kk += 256)
            st[kk * ST20 + r] = g_sln[(i0 + r) * CS + kk];

    const int NC = CS / 16;
    float4 ldr[4];
    #pragma unroll
    for (int iL = 0; iL < 4; iL++) {
        int idx = t + iL * 256;
        int mat = idx >> 9, rem = idx & 511, kr = rem >> 5, c4 = rem & 31;
        const float* w = mat ? wns : ws;
        ldr[iL] = *(const float4*)(w + (size_t)kr * CS + c0 + c4 * 4);
    }
    #pragma unroll
    for (int iL = 0; iL < 4; iL++) {
        int idx = t + iL * 256;
        int mat = idx >> 9, rem = idx & 511, kr = rem >> 5, c4 = rem & 31;
        *(float4*)&wbf[mat * 2048 + kr * 128 + c4 * 4] = ldr[iL];
    }
    __syncthreads();

    u64 a1[4], a2[4];
    #pragma unroll
    for (int p = 0; p < 4; p++) { a1[p] = 0ull; a2[p] = 0ull; }
    for (int ch = 0; ch < NC; ch++) {
        int cur = ch & 1;
        if (ch + 1 < NC) {
            int k0 = (ch + 1) * 16;
            #pragma unroll
            for (int iL = 0; iL < 4; iL++) {
                int idx = t + iL * 256;
                int mat = idx >> 9, rem = idx & 511, kr = rem >> 5, c4 = rem & 31;
                const float* w = mat ? wns : ws;
                ldr[iL] = *(const float4*)(w + (size_t)(k0 + kr) * CS + c0 + c4 * 4);
            }
        }
        #pragma unroll
        for (int kk = 0; kk < 16; kk++) {
            int k = ch * 16 + kk;
            float w1 = wbf[cur * 4096 + kk * 128 + tx];
            float w2 = wbf[cur * 4096 + 2048 + kk * 128 + tx];
            u64 w1p = pk2(w1, w1), w2p = pk2(w2, w2);
            const u64* sp = (const u64*)&st[k * ST20 + ty * 8];
            #pragma unroll
            for (int p = 0; p < 4; p++) {
                a1[p] = ffma2(sp[p], w1p, a1[p]);
                a2[p] = ffma2(sp[p], w2p, a2[p]);
            }
        }
        if (ch + 1 < NC) {
            int nb = (ch + 1) & 1;
            #pragma unroll
            for (int iL = 0; iL < 4; iL++) {
                int idx = t + iL * 256;
                int mat = idx >> 9, rem = idx & 511, kr = rem >> 5, c4 = rem & 31;
                *(float4*)&wbf[nb * 4096 + mat * 2048 + kr * 128 + c4 * 4] = ldr[iL];
            }
        }
        __syncthreads();
    }
    float bsc = bs[c];
    #pragma unroll
    for (int p = 0; p < 4; p++) {
        float x0, x1, y0, y1;
        upk2(a1[p], x0, x1); upk2(a2[p], y0, y1);
        int r0 = i0 + ty * 8 + 2 * p;
        g_a[r0 * CS + c]       = sigm(x0 + bsc) * g_aln[r0 * CS + c]       + y0;
        g_a[(r0 + 1) * CS + c] = sigm(x1 + bsc) * g_aln[(r0 + 1) * CS + c] + y1;
    }
}

// =====================================================================
// Kernel 2: QKV + gate. grid (3,64,4), block 256 (R8 shape).
// =====================================================================
__global__ void __launch_bounds__(256) k_qkvg(const float* __restrict__ wq,
                                              const float* __restrict__ bq,
                                              const float* __restrict__ wk,
                                              const float* __restrict__ wv,
                                              const float* __restrict__ wg) {
    __shared__ __align__(16) float st[CS * ST20];
    __shared__ __align__(16) float wbf[2 * 16 * 128];
    int t  = threadIdx.x;
    int tx = t & 127, ty = t >> 7;
    int m  = blockIdx.z;
    int i0 = blockIdx.y * 16;
    int c0 = blockIdx.x * 128;
    int c  = c0 + tx;
    const float* w = (m == 0) ? wq : (m == 1) ? wk : (m == 2) ? wv : wg;

    for (int r = 0; r < 16; r++)
        for (int kk = t; kk < CS; kk += 256)
            st[kk * ST20 + r] = g_a[(i0 + r) * CS + kk];

    const int NC = CS / 16;
    float4 ldr[2];
    #pragma unroll
    for (int iL = 0; iL < 2; iL++) {
        int idx = t + iL * 256;
        int kr = idx >> 5, c4 = idx & 31;
        ldr[iL] = *(const float4*)(w + (size_t)kr * CS + c0 + c4 * 4);
    }
    #pragma unroll
    for (int iL = 0; iL < 2; iL++) {
        int idx = t + iL * 256;
        int kr = idx >> 5, c4 = idx & 31;
        *(float4*)&wbf[kr * 128 + c4 * 4] = ldr[iL];
    }
    __syncthreads();

    u64 acc[4];
    #pragma unroll
    for (int p = 0; p < 4; p++) acc[p] = 0ull;
    for (int ch = 0; ch < NC; ch++) {
        int cur = ch & 1;
        if (ch + 1 < NC) {
            int k0 = (ch + 1) * 16;
            #pragma unroll
            for (int iL = 0; iL < 2; iL++) {
                int idx = t + iL * 256;
                int kr = idx >> 5, c4 = idx & 31;
                ldr[iL] = *(const float4*)(w + (size_t)(k0 + kr) * CS + c0 + c4 * 4);
            }
        }
        #pragma unroll
        for (int kk = 0; kk < 16; kk++) {
            int k = ch * 16 + kk;
            float wv_ = wbf[cur * 2048 + kk * 128 + tx];
            u64 wp = pk2(wv_, wv_);
            const u64* sp = (const u64*)&st[k * ST20 + ty * 8];
            #pragma unroll
            for (int p = 0; p < 4; p++) acc[p] = ffma2(sp[p], wp, acc[p]);
        }
        if (ch + 1 < NC) {
            int nb = (ch + 1) & 1;
            #pragma unroll
            for (int iL = 0; iL < 2; iL++) {
                int idx = t + iL * 256;
                int kr = idx >> 5, c4 = idx & 31;
                *(float4*)&wbf[nb * 2048 + kr * 128 + c4 * 4] = ldr[iL];
            }
        }
        __syncthreads();
    }
    int h = c / DH, d = c - h * DH;
    float bqc = (m == 0) ? bq[c] : 0.0f;
    #pragma unroll
    for (int p = 0; p < 4; p++) {
        float v0, v1; upk2(acc[p], v0, v1);
        int r0 = i0 + ty * 8 + 2 * p;
        int idx0 = h * (NSEQ * DH) + r0 * DH + d;
        int idx1 = idx0 + DH;
        if (m == 0)      { g_q[idx0] = (v0 + bqc) * RSQRT_D; g_q[idx1] = (v1 + bqc) * RSQRT_D; }
        else if (m == 1) { g_k[idx0] = v0;                   g_k[idx1] = v1; }
        else if (m == 2) { g_v[idx0] = v0;                   g_v[idx1] = v1; }
        else             { g_g[idx0] = sigm(v0);             g_g[idx1] = sigm(v1); }
    }
}

// =====================================================================
// Kernel G: gate = sigmoid(s_i@ws2 + bs2). grid (3,64), block 256.
// =====================================================================
__global__ void __launch_bounds__(256) k_gate(const float* __restrict__ s_i,
                                              const float* __restrict__ ws2,
                                              const float* __restrict__ bs2) {
    __shared__ __align__(16) float st[CS * ST20];
    __shared__ __align__(16) float wbf[2 * 16 * 128];
    int t  = threadIdx.x;
    int tx = t & 127, ty = t >> 7;
    int i0 = blockIdx.y * 16;
    int c0 = blockIdx.x * 128;
    int c  = c0 + tx;

    for (int r = 0; r < 16; r++)
        for (int kk = t; kk < CS; kk += 256)
            st[kk * ST20 + r] = s_i[(i0 + r) * CS + kk];

    const int NC = CS / 16;
    float4 ldr[2];
    #pragma unroll
    for (int iL = 0; iL < 2; iL++) {
        int idx = t + iL * 256;
        int kr = idx >> 5, c4 = idx & 31;
        ldr[iL] = *(const float4*)(ws2 + (size_t)kr * CS + c0 + c4 * 4);
    }
    #pragma unroll
    for (int iL = 0; iL < 2; iL++) {
        int idx = t + iL * 256;
        int kr = idx >> 5, c4 = idx & 31;
        *(float4*)&wbf[kr * 128 + c4 * 4] = ldr[iL];
    }
    __syncthreads();

    u64 acc[4];
    #pragma unroll
    for (int p = 0; p < 4; p++) acc[p] = 0ull;
    for (int ch = 0; ch < NC; ch++) {
        int cur = ch & 1;
        if (ch + 1 < NC) {
            int k0 = (ch + 1) * 16;
            #pragma unroll
            for (int iL = 0; iL < 2; iL++) {
                int idx = t + iL * 256;
                int kr = idx >> 5, c4 = idx & 31;
                ldr[iL] = *(const float4*)(ws2 + (size_t)(k0 + kr) * CS + c0 + c4 * 4);
            }
        }
        #pragma unroll
        for (int kk = 0; kk < 16; kk++) {
            int k = ch * 16 + kk;
            float wv_ = wbf[cur * 2048 + kk * 128 + tx];
            u64 wp = pk2(wv_, wv_);
            const u64* sp = (const u64*)&st[k * ST20 + ty * 8];
            #pragma unroll
            for (int p = 0; p < 4; p++) acc[p] = ffma2(sp[p], wp, acc[p]);
        }
        if (ch + 1 < NC) {
            int nb = (ch + 1) & 1;
            #pragma unroll
            for (int iL = 0; iL < 2; iL++) {
                int idx = t + iL * 256;
                int kr = idx >> 5, c4 = idx & 31;
                *(float4*)&wbf[nb * 2048 + kr * 128 + c4 * 4] = ldr[iL];
            }
        }
        __syncthreads();
    }
    float bsc = bs2[c];
    #pragma unroll
    for (int p = 0; p < 4; p++) {
        float v0, v1; upk2(acc[p], v0, v1);
        int r0 = i0 + ty * 8 + 2 * p;
        g_gate[r0 * CS + c]       = sigm(v0 + bsc);
        g_gate[(r0 + 1) * CS + c] = sigm(v1 + bsc);
    }
}

// =====================================================================
// Kernel 3: pair bias via tf32 mma.sync tensor cores.
// grid (8,1024), block 128 (4 warps). Per block: S[128j x 16h] =
// Z[128x128] @ W[128x16]; LN stats ride on fp32 A-frag values.
// smem: zs[128][132] + wsm[128][24] (stride-24 -> conflict-free B) +
// sb[16][132] staging for coalesced bias stores.  ~88 KB.
// =====================================================================
#define PAIR_SMEM ((128*132 + 128*24 + 16*132 + 2*NH) * 4)
__global__ void __launch_bounds__(128) k_pair(const float* __restrict__ z) {
    extern __shared__ float sm[];
    float* zs  = sm;                     // [128][132]
    float* wsm = sm + 128 * 132;         // [128][24] tf32 bits
    float* sb  = wsm + 128 * 24;         // [16][132]
    float* WH  = sb + 16 * 132;
    float* CH  = WH + NH;
    int t = threadIdx.x;
    int i = blockIdx.y, j0 = blockIdx.x * 128;
    int lane = t & 31, wid = t >> 5;
    int l4 = lane & 3, l8 = lane >> 2;
    int wbase = wid * 32;

    for (int idx = t; idx < 128 * 24; idx += 128) wsm[idx] = g_wt[idx];
    if (t < NH)          WH[t]      = g_WH[t];
    else if (t < 2 * NH) CH[t - NH] = g_CH[t - NH];

    const float4* zg = (const float4*)(z + (size_t)i * (NSEQ * CZ) + (size_t)j0 * CZ);
    #pragma unroll
    for (int p = 0; p < 32; p++) {
        int f = t + p * 128;
        int jl = f >> 5, c4 = f & 31;
        *(float4*)&zs[jl * 132 + c4 * 4] = zg[(size_t)jl * 32 + c4];
    }
    __syncthreads();

    float acc[2][2][4];
    #pragma unroll
    for (int mt = 0; mt < 2; mt++)
        #pragma unroll
        for (int nt = 0; nt < 2; nt++)
            #pragma unroll
            for (int q = 0; q < 4; q++) acc[mt][nt][q] = 0.0f;
    float sA[2] = {0, 0}, sB[2] = {0, 0}, qA[2] = {0, 0}, qB[2] = {0, 0};

    #pragma unroll
    for (int kst = 0; kst < 16; kst++) {
        int k0 = kst * 8;
        u32 b00 = __float_as_uint(wsm[(k0 + l4) * 24 + l8]);
        u32 b01 = __float_as_uint(wsm[(k0 + l4 + 4) * 24 + l8]);
        u32 b10 = __float_as_uint(wsm[(k0 + l4) * 24 + 8 + l8]);
        u32 b11 = __float_as_uint(wsm[(k0 + l4 + 4) * 24 + 8 + l8]);
        #pragma unroll
        for (int mt = 0; mt < 2; mt++) {
            const float* zr0 = zs + (wbase + mt * 16 + l8) * 132 + k0;
            const float* zr1 = zr0 + 8 * 132;
            float a0o = zr0[l4], a2o = zr0[l4 + 4];
            float a1o = zr1[l4], a3o = zr1[l4 + 4];
            sA[mt] += a0o + a2o;
            qA[mt] = fmaf(a0o, a0o, fmaf(a2o, a2o, qA[mt]));
            sB[mt] += a1o + a3o;
            qB[mt] = fmaf(a1o, a1o, fmaf(a3o, a3o, qB[mt]));
            u32 a0 = cvt_tf32(a0o), a1 = cvt_tf32(a1o);
            u32 a2 = cvt_tf32(a2o), a3 = cvt_tf32(a3o);
            mma_tf32(acc[mt][0], a0, a1, a2, a3, b00, b01);
            mma_tf32(acc[mt][1], a0, a1, a2, a3, b10, b11);
        }
    }
    // reduce LN stats across the 4 lanes sharing a row (xor bits 0,1)
    #pragma unroll
    for (int off = 1; off <= 2; off <<= 1) {
        #pragma unroll
        for (int mt = 0; mt < 2; mt++) {
            sA[mt] += __shfl_xor_sync(0xffffffffu, sA[mt], off);
            sB[mt] += __shfl_xor_sync(0xffffffffu, sB[mt], off);
            qA[mt] += __shfl_xor_sync(0xffffffffu, qA[mt], off);
            qB[mt] += __shfl_xor_sync(0xffffffffu, qB[mt], off);
        }
    }
    float meanA[2], rstdA[2], meanB[2], rstdB[2];
    #pragma unroll
    for (int mt = 0; mt < 2; mt++) {
        meanA[mt] = sA[mt] * (1.0f / CZ);
        rstdA[mt] = rsqrtf(qA[mt] * (1.0f / CZ) - meanA[mt] * meanA[mt] + 1e-5f);
        meanB[mt] = sB[mt] * (1.0f / CZ);
        rstdB[mt] = rsqrtf(qB[mt] * (1.0f / CZ) - meanB[mt] * meanB[mt] + 1e-5f);
    }
    // epilogue: bias into sb[h][j]
    #pragma unroll
    for (int mt = 0; mt < 2; mt++) {
        int r0 = wbase + mt * 16 + l8, r1 = r0 + 8;
        #pragma unroll
        for (int nt = 0; nt < 2; nt++) {
            int h0 = nt * 8 + l4 * 2, h1 = h0 + 1;
            float W0 = WH[h0], W1 = WH[h1], C0 = CH[h0], C1 = CH[h1];
            sb[h0 * 132 + r0] = (acc[mt][nt][0] - meanA[mt] * W0) * rstdA[mt] + C0;
            sb[h1 * 132 + r0] = (acc[mt][nt][1] - meanA[mt] * W1) * rstdA[mt] + C1;
            sb[h0 * 132 + r1] = (acc[mt][nt][2] - meanB[mt] * W0) * rstdB[mt] + C0;
            sb[h1 * 132 + r1] = (acc[mt][nt][3] - meanB[mt] * W1) * rstdB[mt] + C1;
        }
    }
    __syncthreads();
    // coalesced writeout: thread t -> head t>>3, 16 j's
    int h = t >> 3, jseg = (t & 7) * 16;
    float* bo = g_bias + (size_t)h * NN + (size_t)i * NSEQ + j0 + jseg;
    const float* sbp = sb + h * 132 + jseg;
    #pragma unroll
    for (int q = 0; q < 4; q++)
        *(float4*)(bo + q * 4) = *(const float4*)(sbp + q * 4);
}

// =====================================================================
// Kernel 4: two-pass flash attention, 2 query-rows per warp.
// grid (64,16), block 256, dyn smem 208 KB.
// =====================================================================
#define ATT_SMEM (2 * NSEQ * 13 * 8)
__global__ void __launch_bounds__(256) k_attn() {
    extern __shared__ __align__(16) u64 sm8[];
    u64* ks_ = sm8;
    u64* vs_ = sm8 + NSEQ * 13;
    int h  = blockIdx.y;
    int i0 = blockIdx.x * 16;
    int t  = threadIdx.x;
    const float4* kg4 = (const float4*)(g_k + (size_t)h * NSEQ * DH);
    const float4* vg4 = (const float4*)(g_v + (size_t)h * NSEQ * DH);
    for (int idx = t; idx < NSEQ * 6; idx += 256) {
        int j = idx / 6, q4 = idx - j * 6;
        float4 kv = kg4[idx];
        ks_[j * 13 + 2 * q4]     = pk2(kv.x, kv.y);
        ks_[j * 13 + 2 * q4 + 1] = pk2(kv.z, kv.w);
        float4 vv = vg4[idx];
        vs_[j * 13 + 2 * q4]     = pk2(vv.x, vv.y);
        vs_[j * 13 + 2 * q4 + 1] = pk2(vv.z, vv.w);
    }
    __syncthreads();
    int w = t >> 5, lane = t & 31;
    int iA = i0 + 2 * w, iB = iA + 1;

    u64 qpA[12], qpB[12];
    {
        const float4* qgA = (const float4*)(g_q + ((size_t)h * NSEQ + iA) * DH);
        const float4* qgB = (const float4*)(g_q + ((size_t)h * NSEQ + iB) * DH);
        #pragma unroll
        for (int p = 0; p < 6; p++) {
            float4 qa = qgA[p];
            qpA[2 * p]     = pk2(qa.x, qa.y);
            qpA[2 * p + 1] = pk2(qa.z, qa.w);
            float4 qb = qgB[p];
            qpB[2 * p]     = pk2(qb.x, qb.y);
            qpB[2 * p + 1] = pk2(qb.z, qb.w);
        }
    }
    const float* bpA = g_bias + (size_t)h * NN + (size_t)iA * NSEQ;
    const float* bpB = bpA + NSEQ;

    float lgsA[32], lgsB[32];
    float mxA = -1e30f, mxB = -1e30f;
    #pragma unroll
    for (int s = 0; s < 32; s++) {
        int j = s * 32 + lane;
        const u64* kr = ks_ + j * 13;
        u64 a0 = 0ull, a1 = 0ull, b0 = 0ull, b1 = 0ull;
        #pragma unroll
        for (int p = 0; p < 12; p += 2) {
            u64 k0 = kr[p], k1 = kr[p + 1];
            a0 = ffma2(qpA[p],     k0, a0);
            a1 = ffma2(qpA[p + 1], k1, a1);
            b0 = ffma2(qpB[p],     k0, b0);
            b1 = ffma2(qpB[p + 1], k1, b1);
        }
        float x0, x1, y0, y1;
        upk2(a0, x0, x1); upk2(a1, y0, y1);
        float lgA = bpA[j] + ((x0 + x1) + (y0 + y1));
        upk2(b0, x0, x1); upk2(b1, y0, y1);
        float lgB = bpB[j] + ((x0 + x1) + (y0 + y1));
        lgsA[s] = lgA; mxA = fmaxf(mxA, lgA);
        lgsB[s] = lgB; mxB = fmaxf(mxB, lgB);
    }
    #pragma unroll
    for (int off = 16; off > 0; off >>= 1) {
        mxA = fmaxf(mxA, __shfl_xor_sync(0xffffffffu, mxA, off));
        mxB = fmaxf(mxB, __shfl_xor_sync(0xffffffffu, mxB, off));
    }

    float lA = 0.0f, lB = 0.0f;
    u64 oA[12], oB[12];
    #pragma unroll
    for (int p = 0; p < 12; p++) { oA[p] = 0ull; oB[p] = 0ull; }
    #pragma unroll
    for (int s = 0; s < 32; s++) {
        float pA = __expf(lgsA[s] - mxA);
        float pB = __expf(lgsB[s] - mxB);
        lA += pA; lB += pB;
        u64 ppA = pk2(pA, pA), ppB = pk2(pB, pB);
        const u64* vr = vs_ + (s * 32 + lane) * 13;
        #pragma unroll
        for (int q = 0; q < 12; q++) {
            u64 vv = vr[q];
            oA[q] = ffma2(ppA, vv, oA[q]);
            oB[q] = ffma2(ppB, vv, oB[q]);
        }
    }
    #pragma unroll
    for (int off = 16; off > 0; off >>= 1) {
        lA += __shfl_xor_sync(0xffffffffu, lA, off);
        lB += __shfl_xor_sync(0xffffffffu, lB, off);
    }
    float fA[DH], fB[DH];
    #pragma unroll
    for (int q = 0; q < 12; q++) {
        upk2(oA[q], fA[2 * q], fA[2 * q + 1]);
        upk2(oB[q], fB[2 * q], fB[2 * q + 1]);
    }
    #pragma unroll
    for (int d = 0; d < DH; d++) {
        #pragma unroll
        for (int off = 16; off > 0; off >>= 1) {
            fA[d] += __shfl_xor_sync(0xffffffffu, fA[d], off);
            fB[d] += __shfl_xor_sync(0xffffffffu, fB[d], off);
        }
    }
    if (lane == 0) {
        float invA = 1.0f / lA;
        const float* ggA = g_g + ((size_t)h * NSEQ + iA) * DH;
        float* opA = g_o + (size_t)iA * HC + h * DH;
        #pragma unroll
        for (int d = 0; d < DH; d++) opA[d] = fA[d] * invA * ggA[d];
        float invB = 1.0f / lB;
        const float* ggB = g_g + ((size_t)h * NSEQ + iB) * DH;
        float* opB = g_o + (size_t)iB * HC + h * DH;
        #pragma unroll
        for (int d = 0; d < DH; d++) opB[d] = fB[d] * invB * ggB[d];
    }
}

// =====================================================================
// Kernel 5: out = g_gate * (o@wo). grid (3,64), block 256.
// =====================================================================
__global__ void __launch_bounds__(256) k_out2(const float* __restrict__ wo,
                                              float* __restrict__ out) {
    __shared__ __align__(16) float st[CS * ST20];
    __shared__ __align__(16) float wbf[2 * 16 * 128];
    int t  = threadIdx.x;
    int tx = t & 127, ty = t >> 7;
    int i0 = blockIdx.y * 16;
    int c0 = blockIdx.x * 128;
    int c  = c0 + tx;

    for (int r = 0; r < 16; r++)
        for (int kk = t; kk < CS; kk += 256)
            st[kk * ST20 + r] = g_o[(i0 + r) * CS + kk];

    const int NC = CS / 16;
    float4 ldr[2];
    #pragma unroll
    for (int iL = 0; iL < 2; iL++) {
        int idx = t + iL * 256;
        int kr = idx >> 5, c4 = idx & 31;
        ldr[iL] = *(const float4*)(wo + (size_t)kr * CS + c0 + c4 * 4);
    }
    #pragma unroll
    for (int iL = 0; iL < 2; iL++) {
        int idx = t + iL * 256;
        int kr = idx >> 5, c4 = idx & 31;
        *(float4*)&wbf[kr * 128 + c4 * 4] = ldr[iL];
    }
    __syncthreads();

    u64 acc[4];
    #pragma unroll
    for (int p = 0; p < 4; p++) acc[p] = 0ull;
    for (int ch = 0; ch < NC; ch++) {
        int cur = ch & 1;
        if (ch + 1 < NC) {
            int k0 = (ch + 1) * 16;
            #pragma unroll
            for (int iL = 0; iL < 2; iL++) {
                int idx = t + iL * 256;
                int kr = idx >> 5, c4 = idx & 31;
                ldr[iL] = *(const float4*)(wo + (size_t)(k0 + kr) * CS + c0 + c4 * 4);
            }
        }
        #pragma unroll
        for (int kk = 0; kk < 16; kk++) {
            int k = ch * 16 + kk;
            float wv_ = wbf[cur * 2048 + kk * 128 + tx];
            u64 wp = pk2(wv_, wv_);
            const u64* sp = (const u64*)&st[k * ST20 + ty * 8];
            #pragma unroll
            for (int p = 0; p < 4; p++) acc[p] = ffma2(sp[p], wp, acc[p]);
        }
        if (ch + 1 < NC) {
            int nb = (ch + 1) & 1;
            #pragma unroll
            for (int iL = 0; iL < 2; iL++) {
                int idx = t + iL * 256;
                int kr = idx >> 5, c4 = idx & 31;
                *(float4*)&wbf[nb * 2048 + kr * 128 + c4 * 4] = ldr[iL];
            }
        }
        __syncthreads();
    }
    #pragma unroll
    for (int p = 0; p < 4; p++) {
        float v0, v1; upk2(acc[p], v0, v1);
        int r0 = i0 + ty * 8 + 2 * p;
        out[r0 * CS + c]       = g_gate[r0 * CS + c]       * v0;
        out[(r0 + 1) * CS + c] = g_gate[(r0 + 1) * CS + c] * v1;
    }
}

// =====================================================================
extern "C" void kernel_launch(void* const* d_in, const int* in_sizes, int n_in,
                              void* d_out, int out_size) {
    const float* a_i   = (const float*)d_in[0];
    const float* s_i   = (const float*)d_in[1];
    const float* z     = (const float*)d_in[2];
    const float* lns_w = (const float*)d_in[3];
    const float* aws   = (const float*)d_in[4];
    const float* abs_  = (const float*)d_in[5];
    const float* awns  = (const float*)d_in[6];
    const float* wq    = (const float*)d_in[7];
    const float* bq    = (const float*)d_in[8];
    const float* wk    = (const float*)d_in[9];
    const float* wv    = (const float*)d_in[10];
    const float* lnb_w = (const float*)d_in[11];
    const float* lnb_b = (const float*)d_in[12];
    const float* wb    = (const float*)d_in[13];
    const float* wg    = (const float*)d_in[14];
    const float* wo    = (const float*)d_in[15];
    const float* ws2   = (const float*)d_in[16];
    const float* bs2   = (const float*)d_in[17];
    float* out = (float*)d_out;

    static cudaStream_t sA = 0, sB = 0;
    static cudaEvent_t evF = 0, evA = 0, evB = 0;
    static int inited = 0;
    if (!inited) {
        cudaStreamCreateWithFlags(&sA, cudaStreamNonBlocking);
        cudaStreamCreateWithFlags(&sB, cudaStreamNonBlocking);
        cudaEventCreateWithFlags(&evF, cudaEventDisableTiming);
        cudaEventCreateWithFlags(&evA, cudaEventDisableTiming);
        cudaEventCreateWithFlags(&evB, cudaEventDisableTiming);
        cudaFuncSetAttribute(k_pair,  cudaFuncAttributeMaxDynamicSharedMemorySize, PAIR_SMEM);
        cudaFuncSetAttribute(k_attn,  cudaFuncAttributeMaxDynamicSharedMemorySize, ATT_SMEM);
        cudaFuncSetAttribute(k_adaln, cudaFuncAttributeMaxDynamicSharedMemorySize, ADA_SMEM);
        inited = 1;
    }

    // fork
    cudaEventRecord(evF, 0);
    cudaStreamWaitEvent(sA, evF, 0);
    cudaStreamWaitEvent(sB, evF, 0);

    // stream A: pair-bias path (tensor-core)
    k_prep<<<1, 128, 0, sA>>>(lnb_w, lnb_b, wb);
    k_pair<<<dim3(8, NSEQ), 128, PAIR_SMEM, sA>>>(z);

    // stream B: final conditioning gate
    k_gate<<<dim3(3, 64), 256, 0, sB>>>(s_i, ws2, bs2);

    // default stream: AdaLN -> QKV/gate chain
    k_ln<<<NSEQ, CS>>>(a_i, s_i, lns_w);
    k_adaln<<<dim3(3, 64), 256, ADA_SMEM>>>(aws, abs_, awns);
    k_qkvg<<<dim3(3, 64, 4), 256>>>(wq, bq, wk, wv, wg);

    // join
    cudaEventRecord(evA, sA);
    cudaEventRecord(evB, sB);
    cudaStreamWaitEvent(0, evA, 0);
    cudaStreamWaitEvent(0, evB, 0);

    k_attn<<<dim3(64, 16), 256, ATT_SMEM>>>();
    k_out2<<<dim3(3, 64), 256>>>(wo, out);
}

// round 11
// speedup vs baseline: 1.2040x; 1.2040x over previous
#include <cuda_runtime.h>
#include <cuda_bf16.h>
#include <mma.h>
#include <math.h>

#define NSEQ 1024
#define CS   384
#define CZ   128
#define NH   16
#define DH   24
#define HC   384
#define NN   (NSEQ*NSEQ)
#define RSQRT_D 0.2041241452319315f

typedef unsigned long long u64;
typedef unsigned int u32;

__device__ __forceinline__ u64 pk2(float a, float b) {
    u64 r; asm("mov.b64 %0,{%1,%2};" : "=l"(r) : "f"(a), "f"(b)); return r;
}
__device__ __forceinline__ void upk2(u64 v, float& a, float& b) {
    asm("mov.b64 {%0,%1},%2;" : "=f"(a), "=f"(b) : "l"(v));
}
__device__ __forceinline__ u64 ffma2(u64 a, u64 b, u64 c) {
    u64 d; asm("fma.rn.f32x2 %0,%1,%2,%3;" : "=l"(d) : "l"(a), "l"(b), "l"(c)); return d;
}
__device__ __forceinline__ u64 fadd2(u64 a, u64 b) {
    u64 d; asm("add.rn.f32x2 %0,%1,%2;" : "=l"(d) : "l"(a), "l"(b)); return d;
}
__device__ __forceinline__ float sigm(float x) { return 1.0f / (1.0f + __expf(-x)); }

// ------------- scratch (static device globals) -------------
__device__ float g_aln[NSEQ * CS];
__device__ float g_sln[NSEQ * CS];
__device__ float g_a  [NSEQ * CS];
__device__ float g_t  [2 * NSEQ * CS];      // adaln GEMM temporaries
__device__ float g_q  [NH * NSEQ * DH];
__device__ float g_k  [NH * NSEQ * DH];
__device__ float g_v  [NH * NSEQ * DH];
__device__ float g_g  [NH * NSEQ * DH];
__device__ float g_bias[(size_t)NH * NN];   // [h][i][j], 64 MB
__device__ float g_o  [NSEQ * HC];
__device__ float g_gate[NSEQ * CS];
__device__ u64   g_wpk[NH * 64];
__device__ float g_WH[NH];
__device__ float g_CH[NH];

// =====================================================================
// Kernel P: one-time prep of pair-bias weights (ffma2-packed; R8 form).
// =====================================================================
__global__ void __launch_bounds__(128) k_prep(const float* __restrict__ lnw,
                                              const float* __restrict__ lnb,
                                              const float* __restrict__ wb) {
    int t = threadIdx.x;
    for (int idx = t; idx < NH * 64; idx += 128) {
        int h = idx >> 6, c2 = idx & 63;
        g_wpk[idx] = pk2(lnw[2*c2]     * wb[(2*c2)     * NH + h],
                         lnw[2*c2 + 1] * wb[(2*c2 + 1) * NH + h]);
    }
    if (t < NH) {
        float W = 0, C = 0;
        #pragma unroll 4
        for (int cc = 0; cc < CZ; cc++) {
            float wv = wb[cc * NH + t];
            W += lnw[cc] * wv; C += lnb[cc] * wv;
        }
        g_WH[t] = W; g_CH[t] = C;
    }
}

// =====================================================================
// Kernel 0: row layer norms of a_i and s_i.  grid 1024, block 384.
// =====================================================================
__global__ void __launch_bounds__(384) k_ln(const float* __restrict__ a_i,
                                            const float* __restrict__ s_i,
                                            const float* __restrict__ lnw) {
    __shared__ float red[12][4];
    __shared__ float bcv[4];
    int i = blockIdx.x, t = threadIdx.x;
    float av = a_i[i * CS + t];
    float sv = s_i[i * CS + t];
    float r0 = av, r1 = av * av, r2 = sv, r3 = sv * sv;
    #pragma unroll
    for (int o = 16; o > 0; o >>= 1) {
        r0 += __shfl_down_sync(0xffffffffu, r0, o);
        r1 += __shfl_down_sync(0xffffffffu, r1, o);
        r2 += __shfl_down_sync(0xffffffffu, r2, o);
        r3 += __shfl_down_sync(0xffffffffu, r3, o);
    }
    if ((t & 31) == 0) { int w = t >> 5; red[w][0]=r0; red[w][1]=r1; red[w][2]=r2; red[w][3]=r3; }
    __syncthreads();
    if (t == 0) {
        float s0=0, s1=0, s2=0, s3=0;
        #pragma unroll
        for (int w = 0; w < 12; w++) { s0+=red[w][0]; s1+=red[w][1]; s2+=red[w][2]; s3+=red[w][3]; }
        float ma = s0 * (1.0f/CS), ms = s2 * (1.0f/CS);
        float va = s1 * (1.0f/CS) - ma*ma;
        float vs = s3 * (1.0f/CS) - ms*ms;
        bcv[0]=ma; bcv[1]=rsqrtf(va + 1e-5f);
        bcv[2]=ms; bcv[3]=rsqrtf(vs + 1e-5f);
    }
    __syncthreads();
    g_aln[i*CS + t] = (av - bcv[0]) * bcv[1];
    g_sln[i*CS + t] = (sv - bcv[2]) * bcv[3] * lnw[t];
}

// =====================================================================
// Generic tf32 wmma GEMM: C[64x64] tile of A[1024x384] @ W[384x384].
// Whole K staged once: Asm 64x392 (tf32), Wsm 384x72 (tf32) -> 211 KB.
// block 256 (8 warps: 4 row x 2 col, warp tile 16x32), grid (6,16,nz).
// Epilogue by mode:
//   0: g_t[z]        <- raw
//   1: qkvg scatter  (z: 0=q,1=k,2=v,3=g)
//   2: g_gate        <- sigm(v + bias)
//   3: outp          <- g_gate * v
// A source by asel: 0=g_sln, 1=g_a, 2=param A, 3=g_o.
// =====================================================================
#define ALD 392
#define WLD 72
#define GEMM_SMEM ((64 * ALD + CS * WLD) * 4)
using namespace nvcuda;

__global__ void __launch_bounds__(256) k_gemm(const float* __restrict__ Aext,
                                              const float* __restrict__ W0,
                                              const float* __restrict__ W1,
                                              const float* __restrict__ W2,
                                              const float* __restrict__ W3,
                                              const float* __restrict__ bias,
                                              float* __restrict__ outp,
                                              int asel, int mode) {
    extern __shared__ float gsm[];
    float* Asm = gsm;
    float* Wsm = gsm + 64 * ALD;
    float* Csm = Wsm;                      // reused after mma loop
    int t = threadIdx.x, w = t >> 5;
    int i0 = blockIdx.y * 64;
    int c0 = blockIdx.x * 64;
    int z  = blockIdx.z;
    const float* Ap = (asel == 0) ? g_sln : (asel == 1) ? g_a : (asel == 2) ? Aext : g_o;
    const float* W  = (z == 0) ? W0 : (z == 1) ? W1 : (z == 2) ? W2 : W3;

    // stage A band [64 x 384] as tf32
    const float4* A4 = (const float4*)(Ap + (size_t)i0 * CS);
    #pragma unroll
    for (int p = 0; p < 24; p++) {
        int idx = t + p * 256;
        int row = idx / 96, c4 = idx % 96;
        float4 v = A4[row * 96 + c4];
        float* dst = Asm + row * ALD + c4 * 4;
        dst[0] = wmma::__float_to_tf32(v.x);
        dst[1] = wmma::__float_to_tf32(v.y);
        dst[2] = wmma::__float_to_tf32(v.z);
        dst[3] = wmma::__float_to_tf32(v.w);
    }
    // stage W band [384 x 64] as tf32
    #pragma unroll
    for (int p = 0; p < 24; p++) {
        int idx = t + p * 256;
        int row = idx >> 4, c4 = idx & 15;
        float4 v = *(const float4*)(W + (size_t)row * CS + c0 + c4 * 4);
        float* dst = Wsm + row * WLD + c4 * 4;
        dst[0] = wmma::__float_to_tf32(v.x);
        dst[1] = wmma::__float_to_tf32(v.y);
        dst[2] = wmma::__float_to_tf32(v.z);
        dst[3] = wmma::__float_to_tf32(v.w);
    }
    __syncthreads();

    wmma::fragment<wmma::matrix_a, 16, 16, 8, wmma::precision::tf32, wmma::row_major> fa;
    wmma::fragment<wmma::matrix_b, 16, 16, 8, wmma::precision::tf32, wmma::row_major> fb0, fb1;
    wmma::fragment<wmma::accumulator, 16, 16, 8, float> fc0, fc1;
    wmma::fill_fragment(fc0, 0.0f);
    wmma::fill_fragment(fc1, 0.0f);
    int wr = w >> 1, wc = w & 1;
    const float* abase = Asm + wr * 16 * ALD;
    const float* bbase = Wsm + wc * 32;
    #pragma unroll 8
    for (int k = 0; k < 48; k++) {
        wmma::load_matrix_sync(fa, abase + k * 8, ALD);
        wmma::load_matrix_sync(fb0, bbase + k * 8 * WLD, WLD);
        wmma::load_matrix_sync(fb1, bbase + k * 8 * WLD + 16, WLD);
        wmma::mma_sync(fc0, fa, fb0, fc0);
        wmma::mma_sync(fc1, fa, fb1, fc1);
    }
    __syncthreads();
    wmma::store_matrix_sync(Csm + wr * 16 * WLD + wc * 32, fc0, WLD, wmma::mem_row_major);
    wmma::store_matrix_sync(Csm + wr * 16 * WLD + wc * 32 + 16, fc1, WLD, wmma::mem_row_major);
    __syncthreads();

    #pragma unroll
    for (int p = 0; p < 16; p++) {
        int idx = t + p * 256;
        int r = idx >> 6, c = idx & 63;
        float v = Csm[r * WLD + c];
        int gi = i0 + r, gc = c0 + c;
        if (mode == 0) {
            g_t[(size_t)z * (NSEQ * CS) + gi * CS + gc] = v;
        } else if (mode == 1) {
            int h = gc / DH, d = gc - h * DH;
            int oidx = h * (NSEQ * DH) + gi * DH + d;
            if (z == 0)      g_q[oidx] = (v + bias[gc]) * RSQRT_D;
            else if (z == 1) g_k[oidx] = v;
            else if (z == 2) g_v[oidx] = v;
            else             g_g[oidx] = sigm(v);
        } else if (mode == 2) {
            g_gate[gi * CS + gc] = sigm(v + bias[gc]);
        } else {
            outp[gi * CS + gc] = g_gate[gi * CS + gc] * v;
        }
    }
}

// =====================================================================
// AdaLN elementwise epilogue: a = sigm(t1+bs)*aln + t2. grid 1024, blk 384.
// =====================================================================
__global__ void __launch_bounds__(384) k_adaln_ep(const float* __restrict__ bs) {
    int i = blockIdx.x, c = threadIdx.x;
    int idx = i * CS + c;
    g_a[idx] = sigm(g_t[idx] + bs[c]) * g_aln[idx] + g_t[NSEQ * CS + idx];
}

// =====================================================================
// Kernel 3: pair bias (R8 ffma2 version). grid (8,1024), block 128.
// =====================================================================
#define PAIR_SMEM (128*132*4 + NH*64*8 + 2*NH*4)
__global__ void __launch_bounds__(128) k_pair(const float* __restrict__ z) {
    extern __shared__ float sm[];
    float* zs  = sm;
    u64*   wsm = (u64*)(sm + 128 * 132);
    float* WH  = (float*)(wsm + NH * 64);
    float* CH  = WH + NH;
    int t  = threadIdx.x;
    int i  = blockIdx.y;
    int j0 = blockIdx.x * 128;

    #pragma unroll
    for (int p = 0; p < 8; p++) wsm[t + p * 128] = g_wpk[t + p * 128];
    if (t < NH)            WH[t]      = g_WH[t];
    else if (t < 2 * NH)   CH[t - NH] = g_CH[t - NH];

    const float4* zg = (const float4*)(z + (size_t)i * (NSEQ * CZ) + (size_t)j0 * CZ);
    #pragma unroll
    for (int p = 0; p < 32; p++) {
        int f = t + p * 128;
        int jl = f >> 5, c4 = f & 31;
        *(float4*)&zs[jl * 132 + c4 * 4] = zg[(size_t)jl * 32 + c4];
    }
    __syncthreads();

    u64 acc[NH];
    #pragma unroll
    for (int h = 0; h < NH; h++) acc[h] = 0ull;
    u64 s2 = 0ull, q2 = 0ull;
    const float* zr = zs + t * 132;
    #pragma unroll 8
    for (int c4 = 0; c4 < 32; c4++) {
        float4 v = *(const float4*)&zr[c4 * 4];
        u64 v01 = pk2(v.x, v.y), v23 = pk2(v.z, v.w);
        s2 = fadd2(s2, fadd2(v01, v23));
        q2 = ffma2(v01, v01, q2);
        q2 = ffma2(v23, v23, q2);
        const u64* base = wsm + 2 * c4;
        #pragma unroll
        for (int h = 0; h < NH; h++) {
            ulonglong2 wv2 = *(const ulonglong2*)(base + h * 64);
            acc[h] = ffma2(v01, wv2.x, acc[h]);
            acc[h] = ffma2(v23, wv2.y, acc[h]);
        }
    }
    float sa, sb, qa, qb;
    upk2(s2, sa, sb); upk2(q2, qa, qb);
    float mean = (sa + sb) * (1.0f / CZ);
    float var  = (qa + qb) * (1.0f / CZ) - mean * mean;
    float rstd = rsqrtf(var + 1e-5f);
    int j = j0 + t;
    float* bo = g_bias + (size_t)i * NSEQ + j;
    #pragma unroll
    for (int h = 0; h < NH; h++) {
        float x0, x1; upk2(acc[h], x0, x1);
        bo[(size_t)h * NN] = ((x0 + x1) - mean * WH[h]) * rstd + CH[h];
    }
}

// =====================================================================
// Kernel 4: two-pass flash attention, 2 query-rows per warp (R8).
// grid (64,16), block 256, dyn smem 208 KB.
// =====================================================================
#define ATT_SMEM (2 * NSEQ * 13 * 8)
__global__ void __launch_bounds__(256) k_attn() {
    extern __shared__ __align__(16) u64 sm8[];
    u64* ks_ = sm8;
    u64* vs_ = sm8 + NSEQ * 13;
    int h  = blockIdx.y;
    int i0 = blockIdx.x * 16;
    int t  = threadIdx.x;
    const float4* kg4 = (const float4*)(g_k + (size_t)h * NSEQ * DH);
    const float4* vg4 = (const float4*)(g_v + (size_t)h * NSEQ * DH);
    for (int idx = t; idx < NSEQ * 6; idx += 256) {
        int j = idx / 6, q4 = idx - j * 6;
        float4 kv = kg4[idx];
        ks_[j * 13 + 2 * q4]     = pk2(kv.x, kv.y);
        ks_[j * 13 + 2 * q4 + 1] = pk2(kv.z, kv.w);
        float4 vv = vg4[idx];
        vs_[j * 13 + 2 * q4]     = pk2(vv.x, vv.y);
        vs_[j * 13 + 2 * q4 + 1] = pk2(vv.z, vv.w);
    }
    __syncthreads();
    int w = t >> 5, lane = t & 31;
    int iA = i0 + 2 * w, iB = iA + 1;

    u64 qpA[12], qpB[12];
    {
        const float4* qgA = (const float4*)(g_q + ((size_t)h * NSEQ + iA) * DH);
        const float4* qgB = (const float4*)(g_q + ((size_t)h * NSEQ + iB) * DH);
        #pragma unroll
        for (int p = 0; p < 6; p++) {
            float4 qa = qgA[p];
            qpA[2 * p]     = pk2(qa.x, qa.y);
            qpA[2 * p + 1] = pk2(qa.z, qa.w);
            float4 qb = qgB[p];
            qpB[2 * p]     = pk2(qb.x, qb.y);
            qpB[2 * p + 1] = pk2(qb.z, qb.w);
        }
    }
    const float* bpA = g_bias + (size_t)h * NN + (size_t)iA * NSEQ;
    const float* bpB = bpA + NSEQ;

    float lgsA[32], lgsB[32];
    float mxA = -1e30f, mxB = -1e30f;
    #pragma unroll
    for (int s = 0; s < 32; s++) {
        int j = s * 32 + lane;
        const u64* kr = ks_ + j * 13;
        u64 a0 = 0ull, a1 = 0ull, b0 = 0ull, b1 = 0ull;
        #pragma unroll
        for (int p = 0; p < 12; p += 2) {
            u64 k0 = kr[p], k1 = kr[p + 1];
            a0 = ffma2(qpA[p],     k0, a0);
            a1 = ffma2(qpA[p + 1], k1, a1);
            b0 = ffma2(qpB[p],     k0, b0);
            b1 = ffma2(qpB[p + 1], k1, b1);
        }
        float x0, x1, y0, y1;
        upk2(a0, x0, x1); upk2(a1, y0, y1);
        float lgA = bpA[j] + ((x0 + x1) + (y0 + y1));
        upk2(b0, x0, x1); upk2(b1, y0, y1);
        float lgB = bpB[j] + ((x0 + x1) + (y0 + y1));
        lgsA[s] = lgA; mxA = fmaxf(mxA, lgA);
        lgsB[s] = lgB; mxB = fmaxf(mxB, lgB);
    }
    #pragma unroll
    for (int off = 16; off > 0; off >>= 1) {
        mxA = fmaxf(mxA, __shfl_xor_sync(0xffffffffu, mxA, off));
        mxB = fmaxf(mxB, __shfl_xor_sync(0xffffffffu, mxB, off));
    }

    float lA = 0.0f, lB = 0.0f;
    u64 oA[12], oB[12];
    #pragma unroll
    for (int p = 0; p < 12; p++) { oA[p] = 0ull; oB[p] = 0ull; }
    #pragma unroll
    for (int s = 0; s < 32; s++) {
        float pA = __expf(lgsA[s] - mxA);
        float pB = __expf(lgsB[s] - mxB);
        lA += pA; lB += pB;
        u64 ppA = pk2(pA, pA), ppB = pk2(pB, pB);
        const u64* vr = vs_ + (s * 32 + lane) * 13;
        #pragma unroll
        for (int q = 0; q < 12; q++) {
            u64 vv = vr[q];
            oA[q] = ffma2(ppA, vv, oA[q]);
            oB[q] = ffma2(ppB, vv, oB[q]);
        }
    }
    #pragma unroll
    for (int off = 16; off > 0; off >>= 1) {
        lA += __shfl_xor_sync(0xffffffffu, lA, off);
        lB += __shfl_xor_sync(0xffffffffu, lB, off);
    }
    float fA[DH], fB[DH];
    #pragma unroll
    for (int q = 0; q < 12; q++) {
        upk2(oA[q], fA[2 * q], fA[2 * q + 1]);
        upk2(oB[q], fB[2 * q], fB[2 * q + 1]);
    }
    #pragma unroll
    for (int d = 0; d < DH; d++) {
        #pragma unroll
        for (int off = 16; off > 0; off >>= 1) {
            fA[d] += __shfl_xor_sync(0xffffffffu, fA[d], off);
            fB[d] += __shfl_xor_sync(0xffffffffu, fB[d], off);
        }
    }
    if (lane == 0) {
        float invA = 1.0f / lA;
        const float* ggA = g_g + ((size_t)h * NSEQ + iA) * DH;
        float* opA = g_o + (size_t)iA * HC + h * DH;
        #pragma unroll
        for (int d = 0; d < DH; d++) opA[d] = fA[d] * invA * ggA[d];
        float invB = 1.0f / lB;
        const float* ggB = g_g + ((size_t)h * NSEQ + iB) * DH;
        float* opB = g_o + (size_t)iB * HC + h * DH;
        #pragma unroll
        for (int d = 0; d < DH; d++) opB[d] = fB[d] * invB * ggB[d];
    }
}

// =====================================================================
extern "C" void kernel_launch(void* const* d_in, const int* in_sizes, int n_in,
                              void* d_out, int out_size) {
    const float* a_i   = (const float*)d_in[0];
    const float* s_i   = (const float*)d_in[1];
    const float* z     = (const float*)d_in[2];
    const float* lns_w = (const float*)d_in[3];
    const float* aws   = (const float*)d_in[4];
    const float* abs_  = (const float*)d_in[5];
    const float* awns  = (const float*)d_in[6];
    const float* wq    = (const float*)d_in[7];
    const float* bq    = (const float*)d_in[8];
    const float* wk    = (const float*)d_in[9];
    const float* wv    = (const float*)d_in[10];
    const float* lnb_w = (const float*)d_in[11];
    const float* lnb_b = (const float*)d_in[12];
    const float* wb    = (const float*)d_in[13];
    const float* wg    = (const float*)d_in[14];
    const float* wo    = (const float*)d_in[15];
    const float* ws2   = (const float*)d_in[16];
    const float* bs2   = (const float*)d_in[17];
    float* out = (float*)d_out;

    static cudaStream_t sA = 0, sB = 0;
    static cudaEvent_t evF = 0, evA = 0, evB = 0;
    static int inited = 0;
    if (!inited) {
        cudaStreamCreateWithFlags(&sA, cudaStreamNonBlocking);
        cudaStreamCreateWithFlags(&sB, cudaStreamNonBlocking);
        cudaEventCreateWithFlags(&evF, cudaEventDisableTiming);
        cudaEventCreateWithFlags(&evA, cudaEventDisableTiming);
        cudaEventCreateWithFlags(&evB, cudaEventDisableTiming);
        cudaFuncSetAttribute(k_pair, cudaFuncAttributeMaxDynamicSharedMemorySize, PAIR_SMEM);
        cudaFuncSetAttribute(k_attn, cudaFuncAttributeMaxDynamicSharedMemorySize, ATT_SMEM);
        cudaFuncSetAttribute(k_gemm, cudaFuncAttributeMaxDynamicSharedMemorySize, GEMM_SMEM);
        inited = 1;
    }

    // fork
    cudaEventRecord(evF, 0);
    cudaStreamWaitEvent(sA, evF, 0);
    cudaStreamWaitEvent(sB, evF, 0);

    // stream A: pair-bias path (ffma2, R8-proven)
    k_prep<<<1, 128, 0, sA>>>(lnb_w, lnb_b, wb);
    k_pair<<<dim3(8, NSEQ), 128, PAIR_SMEM, sA>>>(z);

    // stream B: final conditioning gate (tensor-core)
    k_gemm<<<dim3(6, 16, 1), 256, GEMM_SMEM, sB>>>(s_i, ws2, nullptr, nullptr, nullptr,
                                                   bs2, nullptr, /*asel=*/2, /*mode=*/2);

    // default stream: LN -> AdaLN (2 mma GEMMs + elementwise) -> QKV/gate (z=4)
    k_ln<<<NSEQ, CS>>>(a_i, s_i, lns_w);
    k_gemm<<<dim3(6, 16, 2), 256, GEMM_SMEM>>>(nullptr, aws, awns, nullptr, nullptr,
                                               nullptr, nullptr, /*asel=*/0, /*mode=*/0);
    k_adaln_ep<<<NSEQ, CS>>>(abs_);
    k_gemm<<<dim3(6, 16, 4), 256, GEMM_SMEM>>>(nullptr, wq, wk, wv, wg,
                                               bq, nullptr, /*asel=*/1, /*mode=*/1);

    // join
    cudaEventRecord(evA, sA);
    cudaEventRecord(evB, sB);
    cudaStreamWaitEvent(0, evA, 0);
    cudaStreamWaitEvent(0, evB, 0);

    k_attn<<<dim3(64, 16), 256, ATT_SMEM>>>();
    k_gemm<<<dim3(6, 16, 1), 256, GEMM_SMEM>>>(nullptr, wo, nullptr, nullptr, nullptr,
                                               nullptr, out, /*asel=*/3, /*mode=*/3);
}